// round 6
// baseline (speedup 1.0000x reference)
#include <cuda_runtime.h>
#include <cuda_bf16.h>
#include <cstdint>

// Problem constants
#define BDIM 128   // batch (both sat and grd)
#define HDIM 4
#define WDIM 64
#define CDIM 16
#define FEAT (HDIM*WDIM*CDIM)   // 4096 floats per image

// Output layout (floats): [sat 524288][grd 524288][distance 16384 (g,s)][orien 16384 (s,g)]
#define OFF_SAT   0
#define OFF_GRD   (BDIM*FEAT)                 // 524288
#define OFF_DIST  (2*BDIM*FEAT)               // 1048576
#define OFF_OR    (2*BDIM*FEAT + BDIM*BDIM)   // 1064960

#define NTHREADS 512

// grd pre-transposed layout: 32 chunks of [c8][kw16][g128] floats (64KB each).
// chunk m = ((h*4 + kq)*2 + cp):  h=m>>3, kq=(m>>1)&3, cp=m&1, c = cp*8+ci, kw = kq*16+kwi
#define CHUNK_FLOATS 16384
__device__ float g_grdT[32 * CHUNK_FLOATS];   // 2 MB static scratch (allowed)

// SMEM: sat duplicated pairs [h][c][w'0..127]{v,v} = 16384 floats,
//       plus 2 x 16384-float grd chunk buffers.
constexpr int SAT_FLOATS  = HDIM*CDIM*128*2;              // 16384
constexpr int SMEM_FLOATS = SAT_FLOATS + 2*CHUNK_FLOATS;  // 49152
constexpr int SMEM_BYTES  = SMEM_FLOATS*4;                // 196608 B

// fma.rn.f32x2 — packed 2-wide fp32 FMA (exact fp32 per lane; PTX-only).
__device__ __forceinline__ void ffma2(unsigned long long& acc,
                                      unsigned long long a,
                                      unsigned long long b)
{
    asm("fma.rn.f32x2 %0, %1, %2, %0;" : "+l"(acc) : "l"(a), "l"(b));
}

__device__ __forceinline__ void cp16(float* smem_dst, const float* gsrc)
{
    unsigned sa = (unsigned)__cvta_generic_to_shared(smem_dst);
    asm volatile("cp.async.cg.shared.global [%0], [%1], 16;\n" :: "r"(sa), "l"(gsrc));
}
#define CP_COMMIT() asm volatile("cp.async.commit_group;\n" ::: "memory")
#define CP_WAIT0()  asm volatile("cp.async.wait_group 0;\n" ::: "memory")

// ---- Pre-kernel: transpose grd [g][h][kw][c] -> g_grdT chunks [c][kw][g] ----
__global__ void grd_transpose_kernel(const float* __restrict__ grd)
{
    int o = blockIdx.x * 256 + threadIdx.x;        // 524288 outputs, g contiguous
    int g   = o & 127;
    int kwi = (o >> 7) & 15;
    int ci  = (o >> 11) & 7;
    int m   = o >> 14;
    int cp  = m & 1;
    int kq  = (m >> 1) & 3;
    int h   = m >> 3;
    g_grdT[o] = __ldg(&grd[g*FEAT + h*(WDIM*CDIM) + (kq*16 + kwi)*CDIM + cp*8 + ci]);
}

// One block per sat image s. 512 threads = 16 warps.
//   wj = (t>>5)&7 -> owns j = wj*8 .. wj*8+7
//   gh = t>>8, lane l -> owns g = gh*64 + 2l, 2l+1 (packed f32x2 pair)
__global__ __launch_bounds__(NTHREADS, 1)
void corr_argmax_kernel(const float* __restrict__ sat,
                        const float* __restrict__ grd,
                        float* __restrict__ dist,
                        float* __restrict__ orien)
{
    extern __shared__ float smem[];
    float* sat_s = smem;                 // duplicated pairs: [(h*16+c)*128 + w'] -> {v,v}
    float* bufs  = smem + SAT_FLOATS;    // 2 chunk buffers

    const int s  = blockIdx.x;
    const int t  = threadIdx.x;
    const int w  = t >> 5;
    const int l  = t & 31;
    const int wj = w & 7;
    const int gh = w >> 3;
    const int j0 = wj * 8;
    const int g0 = gh * 64 + l * 2;

    __shared__ float s_warp[16];
    __shared__ float s_norm;

    // Prefetch chunk 0 via cp.async (overlaps with sat staging + norm below)
    {
        const float* src = g_grdT;       // chunk 0
        #pragma unroll
        for (int k = 0; k < 8; ++k)
            cp16(&bufs[(k*NTHREADS + t)*4], &src[(k*NTHREADS + t)*4]);
        CP_COMMIT();
    }

    // Stage sat[s] into smem as duplicated pairs with circular extension w'=0..126
    const float* satb = sat + s * FEAT;
    for (int i = t; i < FEAT/4; i += NTHREADS) {       // 1024 coalesced float4 loads
        int c4 = i & 3;
        int wI = (i >> 2) & 63;
        int h  = i >> 8;
        float4 v = __ldg((const float4*)(satb + h*WDIM*CDIM + wI*CDIM + c4*4));
        float vv[4] = {v.x, v.y, v.z, v.w};
        #pragma unroll
        for (int j = 0; j < 4; ++j) {
            int c = c4*4 + j;
            float2 p = make_float2(vv[j], vv[j]);
            *(float2*)&sat_s[((h*CDIM + c)*128 + wI)*2] = p;
            if (wI < WDIM-1) *(float2*)&sat_s[((h*CDIM + c)*128 + wI + WDIM)*2] = p;
        }
    }

    // ||sat[s]|| (shift-invariant; replaces the per-(s,g) crop norm) — from gmem
    {
        float ss = 0.f;
        for (int i = t; i < FEAT; i += NTHREADS) {
            float v = __ldg(&satb[i]);
            ss += v * v;
        }
        #pragma unroll
        for (int o = 16; o > 0; o >>= 1) ss += __shfl_down_sync(0xffffffffu, ss, o);
        if (l == 0) s_warp[w] = ss;
        __syncthreads();
        if (t == 0) {
            float tot = 0.f;
            #pragma unroll
            for (int i = 0; i < 16; ++i) tot += s_warp[i];
            s_norm = fmaxf(sqrtf(tot), 1e-12f);   // consumed only in epilogue (post-barriers)
        }
    }

    CP_WAIT0();
    __syncthreads();     // chunk 0 + sat_s ready

    // acc2[jj]: packed pair (g0, g0+1) for shift j0+jj
    unsigned long long acc2[8];
    #pragma unroll
    for (int jj = 0; jj < 8; ++jj) acc2[jj] = 0ull;

    // ---- Main loop over 32 chunks, cp.async double-buffered, 1 barrier/chunk ----
    for (int m = 0; m < 32; ++m) {
        if (m + 1 < 32) {                       // prefetch next chunk into other buffer
            const float* src = g_grdT + (m+1)*CHUNK_FLOATS;
            float* dstb = bufs + ((m+1) & 1)*CHUNK_FLOATS;
            #pragma unroll
            for (int k = 0; k < 8; ++k)
                cp16(&dstb[(k*NTHREADS + t)*4], &src[(k*NTHREADS + t)*4]);
            CP_COMMIT();
        }

        const int h  = m >> 3;
        const int kq = (m >> 1) & 3;
        const int cp = m & 1;
        const int kwbase = kq * 16;
        const float* bm = bufs + (m & 1)*CHUNK_FLOATS;

        for (int ci = 0; ci < 8; ++ci) {         // rolled: limits I$ footprint
            const int c = cp*8 + ci;
            // 23-wide a window: duplicated pairs -> direct broadcast LDS.64, no movs
            const float* srow = sat_s + ((h*CDIM + c)*128 + j0 + kwbase)*2;
            unsigned long long ap[23];
            #pragma unroll
            for (int i = 0; i < 23; ++i)
                ap[i] = *(const unsigned long long*)&srow[2*i];

            const float* grow = bm + ci*2048 + g0;
            #pragma unroll
            for (int kw = 0; kw < 16; ++kw) {
                unsigned long long b = *(const unsigned long long*)&grow[kw*128];
                #pragma unroll
                for (int jj = 0; jj < 8; ++jj)
                    ffma2(acc2[jj], ap[kw + jj], b);
            }
        }

        CP_WAIT0();        // next chunk landed
        __syncthreads();   // all readers done with buf[(m+1)&1] from iter m-1; data visible
    }

    // ---- argmax over j (first-max tie-break, matching jnp.argmax) ----
    float* redv = bufs;                  // reuse chunk buffers: 128 g x 8 jgroups
    int*   redj = (int*)(bufs + 1024);
    #pragma unroll
    for (int gg = 0; gg < 2; ++gg) {
        float bv; int bj = j0;
        {
            unsigned u = gg ? (unsigned)(acc2[0] >> 32) : (unsigned)(acc2[0] & 0xffffffffull);
            bv = __uint_as_float(u);
        }
        #pragma unroll
        for (int jj = 1; jj < 8; ++jj) {
            unsigned u = gg ? (unsigned)(acc2[jj] >> 32) : (unsigned)(acc2[jj] & 0xffffffffull);
            float v = __uint_as_float(u);
            if (v > bv) { bv = v; bj = j0 + jj; }   // strict > keeps earliest j
        }
        int g = g0 + gg;
        redv[g*8 + wj] = bv;
        redj[g*8 + wj] = bj;
    }
    __syncthreads();
    if (t < 128) {
        int g = t;
        float bv = redv[g*8]; int bj = redj[g*8];
        #pragma unroll
        for (int i = 1; i < 8; ++i) {                // ascending jgroup == ascending j
            float v = redv[g*8 + i];
            if (v > bv) { bv = v; bj = redj[g*8 + i]; }
        }
        orien[s*BDIM + g] = (float)bj;
        dist[g*BDIM + s]  = 2.0f - 2.0f * (bv / s_norm);
    }
}

extern "C" void kernel_launch(void* const* d_in, const int* in_sizes, int n_in,
                              void* d_out, int out_size)
{
    const float* sat = (const float*)d_in[0];
    const float* grd = (const float*)d_in[1];
    float* out = (float*)d_out;

    // Echo inputs into the output tuple slots (async D2D, graph-capturable).
    cudaMemcpyAsync(out + OFF_SAT, sat, (size_t)BDIM*FEAT*sizeof(float), cudaMemcpyDeviceToDevice);
    cudaMemcpyAsync(out + OFF_GRD, grd, (size_t)BDIM*FEAT*sizeof(float), cudaMemcpyDeviceToDevice);

    // Pre-transpose grd into chunked [c][kw][g] layout (2 MB, ~5-10 us)
    grd_transpose_kernel<<<32*CHUNK_FLOATS/256, 256>>>(grd);

    cudaFuncSetAttribute(corr_argmax_kernel,
                         cudaFuncAttributeMaxDynamicSharedMemorySize, SMEM_BYTES);
    corr_argmax_kernel<<<BDIM, NTHREADS, SMEM_BYTES>>>(sat, grd, out + OFF_DIST, out + OFF_OR);
}

// round 8
// speedup vs baseline: 1.3223x; 1.3223x over previous
#include <cuda_runtime.h>
#include <cuda_bf16.h>
#include <cstdint>

// ---------------- Problem constants ----------------
#define BDIM 128
#define HDIM 4
#define WDIM 64
#define CDIM 16
#define FEAT (HDIM*WDIM*CDIM)   // 4096

// Output layout (floats): [sat 524288][grd 524288][distance 16384 (g,s)][orien 16384 (s,g)]
#define OFF_SAT   0
#define OFF_GRD   (BDIM*FEAT)
#define OFF_DIST  (2*BDIM*FEAT)
#define OFF_OR    (2*BDIM*FEAT + BDIM*BDIM)

// satC: per s, [c16][h4][w'=0..126], 8128 floats. k-order: k=(c*4+h)*64+kw
#define SATC_PER_S 8128
#define ROW_W 127

// ---------------- Static device scratch ----------------
__device__ float g_satCH[BDIM*SATC_PER_S];   // tf32-hi, c-major circular-extended sat
__device__ float g_satCL[BDIM*SATC_PER_S];   // tf32(lo)
__device__ float g_grdTH[4096*BDIM];         // grdT[k][g] hi
__device__ float g_grdTL[4096*BDIM];         // grdT[k][g] lo
__device__ float g_norms[BDIM];

// ---------------- SMEM layout ----------------
// A: hi 8128 + lo 8128 floats = 65024 B
// B: 2 buffers x (hi 64x136 + lo 64x136) = 2 x 69632 B
constexpr int A_FLOATS   = 2*SATC_PER_S;          // 16256
constexpr int BPAD       = 136;                   // padded g-stride (conflict-free frags)
constexpr int BHALF      = 64*BPAD;               // 8704 floats per hi (or lo) chunk
constexpr int BUF_FLOATS = 2*BHALF;               // 17408
constexpr int SMEM_BYTES = (A_FLOATS + 2*BUF_FLOATS)*4;   // 204288 B

// ---------------- PTX helpers (all sm_80-baseline; no 'a'-features) ----------------
__device__ __forceinline__ void cp16(void* smem_dst, const float* gsrc) {
    unsigned sa = (unsigned)__cvta_generic_to_shared(smem_dst);
    asm volatile("cp.async.cg.shared.global [%0], [%1], 16;\n" :: "r"(sa), "l"(gsrc));
}
#define CP_COMMIT() asm volatile("cp.async.commit_group;\n" ::: "memory")
#define CP_WAIT0()  asm volatile("cp.async.wait_group 0;\n" ::: "memory")
#define CP_WAIT1()  asm volatile("cp.async.wait_group 1;\n" ::: "memory")

__device__ __forceinline__ float tf32r(float x) {
    unsigned r;
    asm("cvt.rna.tf32.f32 %0, %1;" : "=r"(r) : "f"(x));
    return __uint_as_float(r);
}
__device__ __forceinline__ void mma8(float* d, const unsigned* a, const unsigned* b) {
    asm("mma.sync.aligned.m16n8k8.row.col.f32.tf32.tf32.f32 "
        "{%0,%1,%2,%3},{%4,%5,%6,%7},{%8,%9},{%0,%1,%2,%3};"
        : "+f"(d[0]), "+f"(d[1]), "+f"(d[2]), "+f"(d[3])
        : "r"(a[0]), "r"(a[1]), "r"(a[2]), "r"(a[3]), "r"(b[0]), "r"(b[1]));
}

// ---------------- Pre-kernels ----------------
__global__ void satsplit_kernel(const float* __restrict__ sat) {
    int i = blockIdx.x * 256 + threadIdx.x;
    if (i >= BDIM*SATC_PER_S) return;
    int s  = i / SATC_PER_S;
    int r  = i - s*SATC_PER_S;
    int c  = r / (HDIM*ROW_W);
    int r2 = r - c*(HDIM*ROW_W);
    int h  = r2 / ROW_W;
    int wp = r2 - h*ROW_W;
    int w  = (wp < WDIM) ? wp : wp - WDIM;          // circular extension
    float v  = __ldg(&sat[((s*HDIM + h)*WDIM + w)*CDIM + c]);
    float hi = __uint_as_float(__float_as_uint(v) & 0xFFFFE000u);   // exact tf32
    g_satCH[i] = hi;
    g_satCL[i] = tf32r(v - hi);
}
__global__ void grdsplit_kernel(const float* __restrict__ grd) {
    int i = blockIdx.x * 256 + threadIdx.x;          // [k][g], k=(c*4+h)*64+kw
    int g  = i & 127;
    int k  = i >> 7;
    int kw = k & 63;
    int h  = (k >> 6) & 3;
    int c  = k >> 8;
    float v  = __ldg(&grd[((g*HDIM + h)*WDIM + kw)*CDIM + c]);
    float hi = __uint_as_float(__float_as_uint(v) & 0xFFFFE000u);
    g_grdTH[i] = hi;
    g_grdTL[i] = tf32r(v - hi);
}
__global__ void norms_kernel(const float* __restrict__ sat) {
    __shared__ float sw[8];
    int s = blockIdx.x, t = threadIdx.x;
    float ss = 0.f;
    for (int i = t; i < FEAT; i += 256) { float v = __ldg(&sat[s*FEAT + i]); ss += v*v; }
    #pragma unroll
    for (int o = 16; o > 0; o >>= 1) ss += __shfl_down_sync(0xffffffffu, ss, o);
    if ((t & 31) == 0) sw[t >> 5] = ss;
    __syncthreads();
    if (t == 0) {
        float tot = 0.f;
        #pragma unroll
        for (int i = 0; i < 8; ++i) tot += sw[i];
        g_norms[s] = fmaxf(sqrtf(tot), 1e-12f);
    }
}

// ---------------- Main kernel: block per s, 256 threads = 8 warps ----------------
// warp w: mrow = (w&1)*32 (j), ncol = (w>>1)*32 (g). Warp tile m32 n32 k8.
// 64 chunks ch = c*4+h, each k64 (kw 0..63), double-buffered B via cp.async.
__global__ __launch_bounds__(256, 1)
void corr_mma_kernel(float* __restrict__ dist, float* __restrict__ orien)
{
    extern __shared__ float smem[];
    float* Ah  = smem;                    // 8128
    float* Al  = smem + SATC_PER_S;       // 8128
    float* bufs = smem + A_FLOATS;        // 2 x BUF_FLOATS

    const int s  = blockIdx.x;
    const int t  = threadIdx.x;
    const int w  = t >> 5;
    const int l  = t & 31;
    const int mrow = (w & 1) * 32;
    const int ncol = (w >> 1) * 32;

    // ---- stage A (whole, hi+lo) + B chunks 0,1 via cp.async ----
    {
        const float* aH = g_satCH + s*SATC_PER_S;
        const float* aL = g_satCL + s*SATC_PER_S;
        #pragma unroll
        for (int i = 0; i < 8; ++i) {
            int u = i*256 + t;                       // 16B unit index, need 2032
            if (u < SATC_PER_S/4) {
                cp16(&Ah[u*4], aH + u*4);
                cp16(&Al[u*4], aL + u*4);
            }
        }
    }
    auto stageB = [&](int ch, int buf) {
        float* bh = bufs + buf*BUF_FLOATS;
        float* bl = bh + BHALF;
        #pragma unroll
        for (int i = 0; i < 8; ++i) {
            int idx = i*256 + t;                     // 2048 units: k' = idx>>5, u = idx&31
            int kp = idx >> 5, u = idx & 31;
            const float* src = g_grdTH + (ch*64 + kp)*128 + u*4;
            cp16(&bh[kp*BPAD + u*4], src);
            cp16(&bl[kp*BPAD + u*4], src + (4096*BDIM - 0) + 0*0 + (g_grdTL - g_grdTH));
        }
    };
    // (lo source computed via pointer diff trick above is fragile; do it explicitly)
    auto stageB2 = [&](int ch, int buf) {
        float* bh = bufs + buf*BUF_FLOATS;
        float* bl = bh + BHALF;
        #pragma unroll
        for (int i = 0; i < 8; ++i) {
            int idx = i*256 + t;
            int kp = idx >> 5, u = idx & 31;
            cp16(&bh[kp*BPAD + u*4], g_grdTH + (ch*64 + kp)*128 + u*4);
            cp16(&bl[kp*BPAD + u*4], g_grdTL + (ch*64 + kp)*128 + u*4);
        }
    };
    stageB2(0, 0);
    CP_COMMIT();          // group: A + B0
    stageB2(1, 1);
    CP_COMMIT();          // group: B1

    float acc[2][4][4];
    #pragma unroll
    for (int f = 0; f < 2; ++f)
        #pragma unroll
        for (int n = 0; n < 4; ++n)
            #pragma unroll
            for (int r = 0; r < 4; ++r) acc[f][n][r] = 0.f;

    const int alane = (l >> 2) + (l & 3);            // A frag lane offset (row + col)
    const int blane = ncol + (l >> 2);               // B frag lane offset

    for (int ch = 0; ch < 64; ++ch) {
        if (ch == 63) { CP_WAIT0(); } else { CP_WAIT1(); }   // B(ch) landed
        __syncthreads();

        const float* bh = bufs + (ch & 1)*BUF_FLOATS;
        const float* bl = bh + BHALF;
        const int abase = ch*ROW_W + mrow + alane;

        #pragma unroll 1
        for (int q = 0; q < 8; ++q) {
            unsigned ah[8], al8[8], bhf[8], blf[8];
            const int ai = abase + 8*q;
            #pragma unroll
            for (int f = 0; f < 2; ++f) {
                ah[f*4+0] = __float_as_uint(Ah[ai + f*16    ]);
                ah[f*4+1] = __float_as_uint(Ah[ai + f*16 + 8]);
                ah[f*4+2] = __float_as_uint(Ah[ai + f*16 + 4]);
                ah[f*4+3] = __float_as_uint(Ah[ai + f*16 +12]);
                al8[f*4+0] = __float_as_uint(Al[ai + f*16    ]);
                al8[f*4+1] = __float_as_uint(Al[ai + f*16 + 8]);
                al8[f*4+2] = __float_as_uint(Al[ai + f*16 + 4]);
                al8[f*4+3] = __float_as_uint(Al[ai + f*16 +12]);
            }
            const int bi = (8*q + (l & 3))*BPAD + blane;
            #pragma unroll
            for (int n = 0; n < 4; ++n) {
                bhf[n*2  ] = __float_as_uint(bh[bi + n*8          ]);
                bhf[n*2+1] = __float_as_uint(bh[bi + n*8 + 4*BPAD ]);
                blf[n*2  ] = __float_as_uint(bl[bi + n*8          ]);
                blf[n*2+1] = __float_as_uint(bl[bi + n*8 + 4*BPAD ]);
            }
            #pragma unroll
            for (int n = 0; n < 4; ++n) {
                mma8(acc[0][n], ah,     bhf + n*2);   // hi*hi
                mma8(acc[1][n], ah + 4, bhf + n*2);
                mma8(acc[0][n], ah,     blf + n*2);   // hi*lo
                mma8(acc[1][n], ah + 4, blf + n*2);
                mma8(acc[0][n], al8,     bhf + n*2);  // lo*hi
                mma8(acc[1][n], al8 + 4, bhf + n*2);
            }
        }
        __syncthreads();                              // all warps done with buf(ch&1)
        if (ch + 2 < 64) { stageB2(ch + 2, ch & 1); CP_COMMIT(); }
    }

    // ---- epilogue: acc -> smem corr[g][j] (pad 65), argmax over j ----
    float* corr_s = bufs;                            // 128*65 floats, B region free now
    #pragma unroll
    for (int f = 0; f < 2; ++f)
        #pragma unroll
        for (int n = 0; n < 4; ++n) {
            const int j = mrow + f*16 + (l >> 2);
            const int g = ncol + n*8 + (l & 3)*2;
            corr_s[(g  )*65 + j    ] = acc[f][n][0];
            corr_s[(g+1)*65 + j    ] = acc[f][n][1];
            corr_s[(g  )*65 + j + 8] = acc[f][n][2];
            corr_s[(g+1)*65 + j + 8] = acc[f][n][3];
        }
    __syncthreads();
    if (t < 128) {
        const int g = t;
        const float* row = corr_s + g*65;
        float bv = row[0]; int bj = 0;
        #pragma unroll
        for (int j = 1; j < 64; ++j) {
            float v = row[j];
            if (v > bv) { bv = v; bj = j; }          // strict > : earliest j (jnp.argmax)
        }
        orien[s*BDIM + g] = (float)bj;
        dist[g*BDIM + s]  = 2.0f - 2.0f * (bv / g_norms[s]);
    }
}

// ---------------- Launcher ----------------
extern "C" void kernel_launch(void* const* d_in, const int* in_sizes, int n_in,
                              void* d_out, int out_size)
{
    const float* sat = (const float*)d_in[0];
    const float* grd = (const float*)d_in[1];
    float* out = (float*)d_out;

    cudaMemcpyAsync(out + OFF_SAT, sat, (size_t)BDIM*FEAT*sizeof(float), cudaMemcpyDeviceToDevice);
    cudaMemcpyAsync(out + OFF_GRD, grd, (size_t)BDIM*FEAT*sizeof(float), cudaMemcpyDeviceToDevice);

    satsplit_kernel<<<(BDIM*SATC_PER_S + 255)/256, 256>>>(sat);
    grdsplit_kernel<<<(4096*BDIM)/256, 256>>>(grd);
    norms_kernel<<<BDIM, 256>>>(sat);

    cudaFuncSetAttribute(corr_mma_kernel,
                         cudaFuncAttributeMaxDynamicSharedMemorySize, SMEM_BYTES);
    corr_mma_kernel<<<BDIM, 256, SMEM_BYTES>>>(out + OFF_DIST, out + OFF_OR);
}